// round 1
// baseline (speedup 1.0000x reference)
#include <cuda_runtime.h>
#include <math.h>

#define BB 4
#define SS 2048
#define EE 768
#define NH 12
#define HD 64
#define M_TOK (BB*SS)      /* 8192 tokens */
#define QKV_N (3*EE)       /* 2304 */

// Scratch (static device arrays — no allocation allowed)
__device__ float g_qkv[(size_t)M_TOK * QKV_N];   // [8192, 2304]
__device__ float g_att[(size_t)M_TOK * EE];      // [8192, 768]

// ---------------------------------------------------------------------------
// Tiled SGEMM with bias: C[M,N] = A[M,K] @ B[K,N] + bias[N]
// 64x64 block tile, BK=16, 256 threads, 4x4 per-thread microtile.
// ---------------------------------------------------------------------------
__global__ void __launch_bounds__(256) gemm_bias_kernel(
    const float* __restrict__ A, const float* __restrict__ B,
    const float* __restrict__ bias, float* __restrict__ C,
    int M, int N, int K)
{
    __shared__ float As[16 * 68];   // As[kk][row]  (A transposed tile)
    __shared__ float Bs[16 * 68];   // Bs[kk][col]

    const int tid = threadIdx.x;
    const int tx = tid & 15;        // col group
    const int ty = tid >> 4;        // row group
    const int row0 = blockIdx.y * 64;
    const int col0 = blockIdx.x * 64;

    float acc[4][4] = {};

    for (int k0 = 0; k0 < K; k0 += 16) {
        // Load A tile 64x16 (coalesced along K)
        #pragma unroll
        for (int i = 0; i < 4; i++) {
            int idx = tid + i * 256;
            int r  = idx >> 4;
            int kk = idx & 15;
            As[kk * 68 + r] = A[(size_t)(row0 + r) * K + k0 + kk];
        }
        // Load B tile 16x64 (coalesced along N)
        #pragma unroll
        for (int i = 0; i < 4; i++) {
            int idx = tid + i * 256;
            int r = idx >> 6;
            int c = idx & 63;
            Bs[r * 68 + c] = B[(size_t)(k0 + r) * N + col0 + c];
        }
        __syncthreads();

        #pragma unroll
        for (int kk = 0; kk < 16; kk++) {
            float4 a4 = *(const float4*)&As[kk * 68 + 4 * ty];
            float4 b4 = *(const float4*)&Bs[kk * 68 + 4 * tx];
            float av[4] = {a4.x, a4.y, a4.z, a4.w};
            float bv[4] = {b4.x, b4.y, b4.z, b4.w};
            #pragma unroll
            for (int i = 0; i < 4; i++)
                #pragma unroll
                for (int j = 0; j < 4; j++)
                    acc[i][j] = fmaf(av[i], bv[j], acc[i][j]);
        }
        __syncthreads();
    }

    #pragma unroll
    for (int i = 0; i < 4; i++) {
        int r = row0 + 4 * ty + i;
        #pragma unroll
        for (int j = 0; j < 4; j++) {
            int c = col0 + 4 * tx + j;
            C[(size_t)r * N + c] = acc[i][j] + bias[c];
        }
    }
}

// ---------------------------------------------------------------------------
// Flash-attention (causal), fp32.
// Grid: (S/64 q-tiles, B*NH). Block: 256 threads (16x16 microtile grid).
// Each thread owns 4 q-rows (ty) x 4 cols (tx) of the 64x64 score tile,
// and a 4x4 O microtile (rows=ty rows, dims=tx dims).
// Row softmax stats are reduced across the 16-lane tx group via shfl_xor;
// all 16 lanes end up with identical (replicated) m/l per row.
// ---------------------------------------------------------------------------
__global__ void __launch_bounds__(256) attn_kernel(
    const float* __restrict__ qkv, float* __restrict__ outp)
{
    extern __shared__ float sm[];
    float* Qt = sm;                 // [d][row]  64x68, q pre-scaled by 1/8
    float* Kt = Qt + 64 * 68;       // [d][col]
    float* Vs = Kt + 64 * 68;       // [key][dim]
    float* Ps = Vs + 64 * 68;       // [row][key]

    const int tid = threadIdx.x;
    const int tx = tid & 15;
    const int ty = tid >> 4;
    const int qt = blockIdx.x;
    const int bh = blockIdx.y;
    const int b = bh / NH;
    const int h = bh % NH;

    const float* base = qkv + (size_t)b * SS * QKV_N;
    const int qcol = h * HD;
    const int kcol = EE + h * HD;
    const int vcol = 2 * EE + h * HD;

    // Load Q tile (scaled by 1/sqrt(64) = 0.125), transposed into smem
    #pragma unroll
    for (int i = 0; i < 16; i++) {
        int idx = tid + i * 256;
        int r = idx >> 6;
        int d = idx & 63;
        Qt[d * 68 + r] = base[(size_t)(qt * 64 + r) * QKV_N + qcol + d] * 0.125f;
    }

    float o[4][4] = {};
    float mrow[4], lrow[4];
    #pragma unroll
    for (int i = 0; i < 4; i++) { mrow[i] = -1e30f; lrow[i] = 0.0f; }

    for (int kt = 0; kt <= qt; kt++) {
        __syncthreads();   // prior iteration's P@V done before overwriting K/V
        #pragma unroll
        for (int i = 0; i < 16; i++) {
            int idx = tid + i * 256;
            int c = idx >> 6;
            int d = idx & 63;
            size_t grow = (size_t)(kt * 64 + c) * QKV_N;
            Kt[d * 68 + c] = base[grow + kcol + d];
            Vs[c * 68 + d] = base[grow + vcol + d];
        }
        __syncthreads();

        // ---- scores S = (Q/8) @ K^T : 64x64x64 mini-GEMM ----
        float s[4][4] = {};
        #pragma unroll
        for (int d = 0; d < 64; d++) {
            float4 q4 = *(const float4*)&Qt[d * 68 + 4 * ty];
            float4 k4 = *(const float4*)&Kt[d * 68 + 4 * tx];
            float qv[4] = {q4.x, q4.y, q4.z, q4.w};
            float kv[4] = {k4.x, k4.y, k4.z, k4.w};
            #pragma unroll
            for (int i = 0; i < 4; i++)
                #pragma unroll
                for (int j = 0; j < 4; j++)
                    s[i][j] = fmaf(qv[i], kv[j], s[i][j]);
        }

        // ---- causal mask on the diagonal tile ----
        if (kt == qt) {
            #pragma unroll
            for (int i = 0; i < 4; i++)
                #pragma unroll
                for (int j = 0; j < 4; j++)
                    if (4 * tx + j > 4 * ty + i) s[i][j] = -1e30f;
        }

        // ---- online softmax (per-row, reduced over the 16-lane tx group) ----
        #pragma unroll
        for (int i = 0; i < 4; i++) {
            float mt = fmaxf(fmaxf(s[i][0], s[i][1]), fmaxf(s[i][2], s[i][3]));
            #pragma unroll
            for (int off = 8; off; off >>= 1)
                mt = fmaxf(mt, __shfl_xor_sync(0xffffffffu, mt, off));
            float mnew = fmaxf(mrow[i], mt);

            float p0 = __expf(s[i][0] - mnew);
            float p1 = __expf(s[i][1] - mnew);
            float p2 = __expf(s[i][2] - mnew);
            float p3 = __expf(s[i][3] - mnew);
            float sum = (p0 + p1) + (p2 + p3);
            #pragma unroll
            for (int off = 8; off; off >>= 1)
                sum += __shfl_xor_sync(0xffffffffu, sum, off);

            float alpha = __expf(mrow[i] - mnew);
            lrow[i] = lrow[i] * alpha + sum;
            mrow[i] = mnew;
            #pragma unroll
            for (int j = 0; j < 4; j++) o[i][j] *= alpha;

            int r = 4 * ty + i;
            Ps[r * 68 + 4 * tx + 0] = p0;
            Ps[r * 68 + 4 * tx + 1] = p1;
            Ps[r * 68 + 4 * tx + 2] = p2;
            Ps[r * 68 + 4 * tx + 3] = p3;
        }
        __syncthreads();

        // ---- O += P @ V : 64x64x64 mini-GEMM ----
        #pragma unroll
        for (int k = 0; k < 64; k++) {
            float4 v4 = *(const float4*)&Vs[k * 68 + 4 * tx];
            #pragma unroll
            for (int i = 0; i < 4; i++) {
                float pp = Ps[(4 * ty + i) * 68 + k];
                o[i][0] = fmaf(pp, v4.x, o[i][0]);
                o[i][1] = fmaf(pp, v4.y, o[i][1]);
                o[i][2] = fmaf(pp, v4.z, o[i][2]);
                o[i][3] = fmaf(pp, v4.w, o[i][3]);
            }
        }
    }

    // ---- normalize and write back in [B,S,E] layout ----
    #pragma unroll
    for (int i = 0; i < 4; i++) {
        float inv = 1.0f / lrow[i];
        int r = qt * 64 + 4 * ty + i;
        size_t rowbase = (size_t)(b * SS + r) * EE + h * HD + 4 * tx;
        #pragma unroll
        for (int j = 0; j < 4; j++)
            outp[rowbase + j] = o[i][j] * inv;
    }
}

// ---------------------------------------------------------------------------
extern "C" void kernel_launch(void* const* d_in, const int* in_sizes, int n_in,
                              void* d_out, int out_size)
{
    (void)in_sizes; (void)n_in; (void)out_size;
    const float* x      = (const float*)d_in[0];
    // d_in[1] = mask  — exactly the strict-upper-triangular causal mask; applied analytically
    const float* W_attn = (const float*)d_in[2];
    const float* b_attn = (const float*)d_in[3];
    const float* W_proj = (const float*)d_in[4];
    const float* b_proj = (const float*)d_in[5];
    float* out = (float*)d_out;

    float* qkv = nullptr;
    float* att = nullptr;
    cudaGetSymbolAddress((void**)&qkv, g_qkv);
    cudaGetSymbolAddress((void**)&att, g_att);

    const int ATTN_SMEM = 4 * 64 * 68 * (int)sizeof(float);  // 69632 B
    cudaFuncSetAttribute(attn_kernel,
                         cudaFuncAttributeMaxDynamicSharedMemorySize, ATTN_SMEM);

    // 1) QKV projection: [8192,768] @ [768,2304] + b_attn
    {
        dim3 grid(QKV_N / 64, M_TOK / 64);
        gemm_bias_kernel<<<grid, 256>>>(x, W_attn, b_attn, qkv,
                                        M_TOK, QKV_N, EE);
    }
    // 2) Causal flash attention per (q-tile, batch*head)
    {
        dim3 grid(SS / 64, BB * NH);
        attn_kernel<<<grid, 256, ATTN_SMEM>>>(qkv, att);
    }
    // 3) Output projection: [8192,768] @ [768,768] + b_proj -> d_out
    {
        dim3 grid(EE / 64, M_TOK / 64);
        gemm_bias_kernel<<<grid, 256>>>(att, W_proj, b_proj, out,
                                        M_TOK, EE, EE);
    }
}

// round 3
// speedup vs baseline: 1.2516x; 1.2516x over previous
#include <cuda_runtime.h>
#include <cuda_bf16.h>
#include <cstdint>
#include <math.h>

#define BB 4
#define SS 2048
#define EE 768
#define NH 12
#define MTOK (BB*SS)      /* 8192 */
#define QKVN (3*EE)       /* 2304 */

// ---------------- scratch (static device arrays; no allocation) -------------
__device__ __align__(256) float         g_qkv [(size_t)MTOK * QKVN];
__device__ __align__(256) __nv_bfloat16 g_xhi [(size_t)MTOK * EE];
__device__ __align__(256) __nv_bfloat16 g_xlo [(size_t)MTOK * EE];
__device__ __align__(256) __nv_bfloat16 g_wahi[(size_t)QKVN * EE];
__device__ __align__(256) __nv_bfloat16 g_walo[(size_t)QKVN * EE];
__device__ __align__(256) __nv_bfloat16 g_wphi[(size_t)EE * EE];
__device__ __align__(256) __nv_bfloat16 g_wplo[(size_t)EE * EE];
__device__ __align__(256) __nv_bfloat16 g_ahi [(size_t)MTOK * EE];
__device__ __align__(256) __nv_bfloat16 g_alo [(size_t)MTOK * EE];

// ---------------- PTX helpers ----------------------------------------------
__device__ __forceinline__ uint32_t smem_u32(const void* p) {
    uint32_t a;
    asm("{ .reg .u64 t; cvta.to.shared.u64 t, %1; cvt.u32.u64 %0, t; }"
        : "=r"(a) : "l"(p));
    return a;
}
#define CP_ASYNC16(sa, g) \
    asm volatile("cp.async.cg.shared.global [%0], [%1], 16;" :: "r"(sa), "l"(g) : "memory")
#define CP_COMMIT() asm volatile("cp.async.commit_group;" ::: "memory")
#define CP_WAIT(n)  asm volatile("cp.async.wait_group %0;" :: "n"(n) : "memory")

__device__ __forceinline__ void ldsm4(uint32_t& r0, uint32_t& r1,
                                      uint32_t& r2, uint32_t& r3, uint32_t a) {
    asm volatile("ldmatrix.sync.aligned.m8n8.x4.shared.b16 {%0,%1,%2,%3}, [%4];"
                 : "=r"(r0), "=r"(r1), "=r"(r2), "=r"(r3) : "r"(a));
}
__device__ __forceinline__ void mma16816(float* c, const uint32_t* a,
                                         const uint32_t* b) {
    asm volatile("mma.sync.aligned.m16n8k16.row.col.f32.bf16.bf16.f32 "
                 "{%0,%1,%2,%3}, {%4,%5,%6,%7}, {%8,%9}, {%0,%1,%2,%3};"
                 : "+f"(c[0]), "+f"(c[1]), "+f"(c[2]), "+f"(c[3])
                 : "r"(a[0]), "r"(a[1]), "r"(a[2]), "r"(a[3]),
                   "r"(b[0]), "r"(b[1]));
}
// SW128 swizzle over 128B rows: 16B-chunk index ^= (row & 7)
__device__ __forceinline__ uint32_t sw_addr(uint32_t base, int row, int chunk) {
    uint32_t off = (uint32_t)(row * 128 + chunk * 16);
    return base + (off ^ ((off >> 3) & 0x70));
}

// ---------------- hi/lo converts --------------------------------------------
__global__ void __launch_bounds__(256) convert_hilo_kernel(
    const float* __restrict__ s, __nv_bfloat16* __restrict__ hi,
    __nv_bfloat16* __restrict__ lo, int n)
{
    int i = blockIdx.x * 256 + threadIdx.x;
    if (i < n) {
        float v = s[i];
        __nv_bfloat16 h = __float2bfloat16(v);
        hi[i] = h;
        lo[i] = __float2bfloat16(v - __bfloat162float(h));
    }
}

__global__ void __launch_bounds__(256) transpose_hilo_kernel(
    const float* __restrict__ W, __nv_bfloat16* __restrict__ Thi,
    __nv_bfloat16* __restrict__ Tlo, int K, int N)   // W[K][N] -> T[N][K]
{
    __shared__ float t[32][33];
    int n0 = blockIdx.x * 32, k0 = blockIdx.y * 32;
    int tx = threadIdx.x, ty = threadIdx.y;
    #pragma unroll
    for (int i = 0; i < 32; i += 8)
        t[ty + i][tx] = W[(size_t)(k0 + ty + i) * N + n0 + tx];
    __syncthreads();
    #pragma unroll
    for (int i = 0; i < 32; i += 8) {
        float v = t[tx][ty + i];
        __nv_bfloat16 h = __float2bfloat16(v);
        size_t o = (size_t)(n0 + ty + i) * K + k0 + tx;
        Thi[o] = h;
        Tlo[o] = __float2bfloat16(v - __bfloat162float(h));
    }
}

// ---------------- HMMA 3-term bf16 GEMM ------------------------------------
// C[M,N] = A[M,K] @ Bt[N,K]^T + bias, A/B as bf16 hi/lo (K-major rows).
// CTA 128x128, 8 warps (2M x 4N), KC=64, 3-stage cp.async, SW128 smem.
#define G3_STAGE   65536        /* 4 tensors x 16KB */
#define G3_STAGES  3
#define G3_SMEM    (G3_STAGES * G3_STAGE)

__device__ __forceinline__ void g3_load_chunk(
    uint32_t sbase, const __nv_bfloat16* Ahi, const __nv_bfloat16* Alo,
    const __nv_bfloat16* Bhi, const __nv_bfloat16* Blo,
    int row0, int col0, int K, int c, int tid)
{
    const __nv_bfloat16* srcs[4];
    srcs[0] = Ahi + (size_t)row0 * K + c * 64;
    srcs[1] = Alo + (size_t)row0 * K + c * 64;
    srcs[2] = Bhi + (size_t)col0 * K + c * 64;
    srcs[3] = Blo + (size_t)col0 * K + c * 64;
    #pragma unroll
    for (int t = 0; t < 4; t++) {
        const __nv_bfloat16* src = srcs[t];
        uint32_t tb = sbase + t * 16384;
        #pragma unroll
        for (int i = 0; i < 4; i++) {
            int idx = tid + i * 256;
            int r = idx >> 3, cb = idx & 7;
            CP_ASYNC16(sw_addr(tb, r, cb), (const void*)(src + (size_t)r * K + cb * 8));
        }
    }
    CP_COMMIT();
}

__global__ void __launch_bounds__(256) gemm3_kernel(
    const __nv_bfloat16* __restrict__ Ahi, const __nv_bfloat16* __restrict__ Alo,
    const __nv_bfloat16* __restrict__ Bhi, const __nv_bfloat16* __restrict__ Blo,
    const float* __restrict__ bias, float* __restrict__ C, int M, int N, int K)
{
    extern __shared__ __align__(1024) char smg[];
    uint32_t sb = smem_u32(smg);
    const int tid = threadIdx.x;
    const int wid = tid >> 5, lid = tid & 31;
    const int wm = (wid >> 2) * 64;      // warp row offset in tile
    const int wn = (wid & 3) * 32;       // warp col offset in tile
    const int lrow = lid & 15;           // ldmatrix row lane
    const int lck  = lid >> 4;           // ldmatrix 16B-chunk lane
    const int row0 = blockIdx.y * 128, col0 = blockIdx.x * 128;
    const int nch = K / 64;

    float acc[4][4][4];
    #pragma unroll
    for (int mi = 0; mi < 4; mi++)
        #pragma unroll
        for (int nj = 0; nj < 4; nj++)
            #pragma unroll
            for (int r = 0; r < 4; r++) acc[mi][nj][r] = 0.0f;

    g3_load_chunk(sb,               Ahi, Alo, Bhi, Blo, row0, col0, K, 0, tid);
    g3_load_chunk(sb + G3_STAGE,    Ahi, Alo, Bhi, Blo, row0, col0, K, 1, tid);
    g3_load_chunk(sb + 2*G3_STAGE,  Ahi, Alo, Bhi, Blo, row0, col0, K, 2, tid);

    for (int c = 0; c < nch; c++) {
        CP_WAIT(2);
        __syncthreads();
        uint32_t st = sb + (uint32_t)(c % G3_STAGES) * G3_STAGE;
        uint32_t bAh = st, bAl = st + 16384, bBh = st + 32768, bBl = st + 49152;

        #pragma unroll
        for (int step = 0; step < 4; step++) {
            int kc = 2 * step;
            uint32_t ah[4][4], al[4][4], bh[4][2], bl[4][2];
            #pragma unroll
            for (int mi = 0; mi < 4; mi++) {
                ldsm4(ah[mi][0], ah[mi][1], ah[mi][2], ah[mi][3],
                      sw_addr(bAh, wm + mi * 16 + lrow, kc + lck));
                ldsm4(al[mi][0], al[mi][1], al[mi][2], al[mi][3],
                      sw_addr(bAl, wm + mi * 16 + lrow, kc + lck));
            }
            #pragma unroll
            for (int g = 0; g < 2; g++) {
                uint32_t r0, r1, r2, r3;
                ldsm4(r0, r1, r2, r3, sw_addr(bBh, wn + g * 16 + lrow, kc + lck));
                bh[2*g][0] = r0; bh[2*g+1][0] = r1; bh[2*g][1] = r2; bh[2*g+1][1] = r3;
                ldsm4(r0, r1, r2, r3, sw_addr(bBl, wn + g * 16 + lrow, kc + lck));
                bl[2*g][0] = r0; bl[2*g+1][0] = r1; bl[2*g][1] = r2; bl[2*g+1][1] = r3;
            }
            #pragma unroll
            for (int mi = 0; mi < 4; mi++)
                #pragma unroll
                for (int nj = 0; nj < 4; nj++) {
                    mma16816(acc[mi][nj], ah[mi], bh[nj]);
                    mma16816(acc[mi][nj], ah[mi], bl[nj]);
                    mma16816(acc[mi][nj], al[mi], bh[nj]);
                }
        }
        __syncthreads();
        if (c + G3_STAGES < nch)
            g3_load_chunk(st, Ahi, Alo, Bhi, Blo, row0, col0, K, c + G3_STAGES, tid);
    }

    // epilogue
    const int gID = lid >> 2, tig = lid & 3;
    #pragma unroll
    for (int mi = 0; mi < 4; mi++) {
        int r = row0 + wm + mi * 16 + gID;
        #pragma unroll
        for (int nj = 0; nj < 4; nj++) {
            int cc = col0 + wn + nj * 8 + tig * 2;
            float b0 = bias[cc], b1 = bias[cc + 1];
            float2 v0 = {acc[mi][nj][0] + b0, acc[mi][nj][1] + b1};
            float2 v1 = {acc[mi][nj][2] + b0, acc[mi][nj][3] + b1};
            *(float2*)&C[(size_t)r * N + cc] = v0;
            *(float2*)&C[(size_t)(r + 8) * N + cc] = v1;
        }
    }
}

// ---------------- causal flash attention (fp32 SIMT, 8x4 microtile) --------
// Grid (S/64, B*NH), 128 threads. Output written as bf16 hi/lo for proj GEMM.
__global__ void __launch_bounds__(128) attn_kernel(
    const float* __restrict__ qkv,
    __nv_bfloat16* __restrict__ ohi, __nv_bfloat16* __restrict__ olo)
{
    extern __shared__ float sm[];
    float* Qt = sm;                 // [d][row] 64x68, Q pre-scaled by 1/8
    float* Kt = Qt + 64 * 68;       // [d][col]
    float* Vs = Kt + 64 * 68;       // [key][dim]
    float* Ps = Vs + 64 * 68;       // [row][key]

    const int tid = threadIdx.x;
    const int tx = tid & 15;        // 4 cols / 4 dims
    const int ty = tid >> 4;        // 8 rows
    const int qt = blockIdx.x;
    const int bh = blockIdx.y;
    const int b = bh / NH, h = bh % NH;

    const float* base = qkv + (size_t)b * SS * QKVN;
    const int qcol = h * 64, kcol = EE + h * 64, vcol = 2 * EE + h * 64;

    #pragma unroll
    for (int i = 0; i < 32; i++) {
        int idx = tid + i * 128;
        int r = idx >> 6, d = idx & 63;
        Qt[d * 68 + r] = base[(size_t)(qt * 64 + r) * QKVN + qcol + d] * 0.125f;
    }

    float o[8][4] = {};
    float mrow[8], lrow[8];
    #pragma unroll
    for (int i = 0; i < 8; i++) { mrow[i] = -1e30f; lrow[i] = 0.0f; }

    for (int kt = 0; kt <= qt; kt++) {
        __syncthreads();
        #pragma unroll
        for (int i = 0; i < 32; i++) {
            int idx = tid + i * 128;
            int c = idx >> 6, d = idx & 63;
            size_t g = (size_t)(kt * 64 + c) * QKVN;
            Kt[d * 68 + c] = base[g + kcol + d];
            Vs[c * 68 + d] = base[g + vcol + d];
        }
        __syncthreads();

        float s[8][4] = {};
        #pragma unroll
        for (int d = 0; d < 64; d++) {
            float4 qa = *(const float4*)&Qt[d * 68 + 8 * ty];
            float4 qb = *(const float4*)&Qt[d * 68 + 8 * ty + 4];
            float4 k4 = *(const float4*)&Kt[d * 68 + 4 * tx];
            float qv[8] = {qa.x, qa.y, qa.z, qa.w, qb.x, qb.y, qb.z, qb.w};
            float kv[4] = {k4.x, k4.y, k4.z, k4.w};
            #pragma unroll
            for (int i = 0; i < 8; i++)
                #pragma unroll
                for (int j = 0; j < 4; j++)
                    s[i][j] = fmaf(qv[i], kv[j], s[i][j]);
        }

        if (kt == qt) {
            #pragma unroll
            for (int i = 0; i < 8; i++)
                #pragma unroll
                for (int j = 0; j < 4; j++)
                    if (4 * tx + j > 8 * ty + i) s[i][j] = -1e30f;
        }

        #pragma unroll
        for (int i = 0; i < 8; i++) {
            float mt = fmaxf(fmaxf(s[i][0], s[i][1]), fmaxf(s[i][2], s[i][3]));
            #pragma unroll
            for (int off = 8; off; off >>= 1)
                mt = fmaxf(mt, __shfl_xor_sync(0xffffffffu, mt, off));
            float mnew = fmaxf(mrow[i], mt);

            float p0 = __expf(s[i][0] - mnew);
            float p1 = __expf(s[i][1] - mnew);
            float p2 = __expf(s[i][2] - mnew);
            float p3 = __expf(s[i][3] - mnew);
            float sum = (p0 + p1) + (p2 + p3);
            #pragma unroll
            for (int off = 8; off; off >>= 1)
                sum += __shfl_xor_sync(0xffffffffu, sum, off);

            float alpha = __expf(mrow[i] - mnew);
            lrow[i] = lrow[i] * alpha + sum;
            mrow[i] = mnew;
            #pragma unroll
            for (int j = 0; j < 4; j++) o[i][j] *= alpha;

            int r = 8 * ty + i;
            Ps[r * 68 + 4 * tx + 0] = p0;
            Ps[r * 68 + 4 * tx + 1] = p1;
            Ps[r * 68 + 4 * tx + 2] = p2;
            Ps[r * 68 + 4 * tx + 3] = p3;
        }
        __syncthreads();

        #pragma unroll
        for (int k0 = 0; k0 < 64; k0 += 4) {
            float4 v0 = *(const float4*)&Vs[(k0 + 0) * 68 + 4 * tx];
            float4 v1 = *(const float4*)&Vs[(k0 + 1) * 68 + 4 * tx];
            float4 v2 = *(const float4*)&Vs[(k0 + 2) * 68 + 4 * tx];
            float4 v3 = *(const float4*)&Vs[(k0 + 3) * 68 + 4 * tx];
            #pragma unroll
            for (int i = 0; i < 8; i++) {
                float4 p = *(const float4*)&Ps[(8 * ty + i) * 68 + k0];
                o[i][0] = fmaf(p.x, v0.x, fmaf(p.y, v1.x, fmaf(p.z, v2.x, fmaf(p.w, v3.x, o[i][0]))));
                o[i][1] = fmaf(p.x, v0.y, fmaf(p.y, v1.y, fmaf(p.z, v2.y, fmaf(p.w, v3.y, o[i][1]))));
                o[i][2] = fmaf(p.x, v0.z, fmaf(p.y, v1.z, fmaf(p.z, v2.z, fmaf(p.w, v3.z, o[i][2]))));
                o[i][3] = fmaf(p.x, v0.w, fmaf(p.y, v1.w, fmaf(p.z, v2.w, fmaf(p.w, v3.w, o[i][3]))));
            }
        }
    }

    #pragma unroll
    for (int i = 0; i < 8; i++) {
        float inv = 1.0f / lrow[i];
        int r = qt * 64 + 8 * ty + i;
        size_t ob = (size_t)(b * SS + r) * EE + h * 64 + 4 * tx;
        #pragma unroll
        for (int j = 0; j < 4; j += 2) {
            float a0 = o[i][j] * inv, a1 = o[i][j + 1] * inv;
            __nv_bfloat16 h0 = __float2bfloat16(a0);
            __nv_bfloat16 h1 = __float2bfloat16(a1);
            __nv_bfloat16 l0 = __float2bfloat16(a0 - __bfloat162float(h0));
            __nv_bfloat16 l1 = __float2bfloat16(a1 - __bfloat162float(h1));
            *reinterpret_cast<__nv_bfloat162*>(&ohi[ob + j]) = __halves2bfloat162(h0, h1);
            *reinterpret_cast<__nv_bfloat162*>(&olo[ob + j]) = __halves2bfloat162(l0, l1);
        }
    }
}

// ---------------------------------------------------------------------------
extern "C" void kernel_launch(void* const* d_in, const int* in_sizes, int n_in,
                              void* d_out, int out_size)
{
    (void)in_sizes; (void)n_in; (void)out_size;
    const float* x      = (const float*)d_in[0];
    // d_in[1] = mask — strict-upper-triangular causal mask, applied analytically
    const float* W_attn = (const float*)d_in[2];
    const float* b_attn = (const float*)d_in[3];
    const float* W_proj = (const float*)d_in[4];
    const float* b_proj = (const float*)d_in[5];
    float* out = (float*)d_out;

    float *qkv; __nv_bfloat16 *xhi, *xlo, *wahi, *walo, *wphi, *wplo, *ahi, *alo;
    cudaGetSymbolAddress((void**)&qkv,  g_qkv);
    cudaGetSymbolAddress((void**)&xhi,  g_xhi);
    cudaGetSymbolAddress((void**)&xlo,  g_xlo);
    cudaGetSymbolAddress((void**)&wahi, g_wahi);
    cudaGetSymbolAddress((void**)&walo, g_walo);
    cudaGetSymbolAddress((void**)&wphi, g_wphi);
    cudaGetSymbolAddress((void**)&wplo, g_wplo);
    cudaGetSymbolAddress((void**)&ahi,  g_ahi);
    cudaGetSymbolAddress((void**)&alo,  g_alo);

    const int ATTN_SMEM = 4 * 64 * 68 * (int)sizeof(float); // 69632
    cudaFuncSetAttribute(gemm3_kernel,
                         cudaFuncAttributeMaxDynamicSharedMemorySize, G3_SMEM);
    cudaFuncSetAttribute(attn_kernel,
                         cudaFuncAttributeMaxDynamicSharedMemorySize, ATTN_SMEM);

    // 0) operand preparation (bf16 hi/lo; weights transposed to [N][K])
    {
        int n = MTOK * EE;
        convert_hilo_kernel<<<(n + 255) / 256, 256>>>(x, xhi, xlo, n);
        transpose_hilo_kernel<<<dim3(QKVN / 32, EE / 32), dim3(32, 8)>>>(
            W_attn, wahi, walo, EE, QKVN);
        transpose_hilo_kernel<<<dim3(EE / 32, EE / 32), dim3(32, 8)>>>(
            W_proj, wphi, wplo, EE, EE);
    }
    // 1) QKV projection (HMMA 3-term): [8192,768]@[768,2304] + b_attn
    gemm3_kernel<<<dim3(QKVN / 128, MTOK / 128), 256, G3_SMEM>>>(
        xhi, xlo, wahi, walo, b_attn, qkv, MTOK, QKVN, EE);
    // 2) causal flash attention -> bf16 hi/lo
    attn_kernel<<<dim3(SS / 64, BB * NH), 128, ATTN_SMEM>>>(qkv, ahi, alo);
    // 3) output projection (HMMA 3-term): [8192,768]@[768,768] + b_proj
    gemm3_kernel<<<dim3(EE / 128, MTOK / 128), 256, G3_SMEM>>>(
        ahi, alo, wphi, wplo, b_proj, out, MTOK, EE, EE);
}

// round 4
// speedup vs baseline: 2.8718x; 2.2944x over previous
#include <cuda_runtime.h>
#include <cuda_bf16.h>
#include <cstdint>
#include <math.h>

#define BB 4
#define SS 2048
#define EE 768
#define NH 12
#define MTOK (BB*SS)      /* 8192 */
#define QKVN (3*EE)       /* 2304 */

// ---------------- scratch (static device arrays; no allocation) -------------
__device__ __align__(256) __nv_bfloat16 g_qkvhi[(size_t)MTOK * QKVN];
__device__ __align__(256) __nv_bfloat16 g_qkvlo[(size_t)MTOK * QKVN];
__device__ __align__(256) __nv_bfloat16 g_xhi [(size_t)MTOK * EE];
__device__ __align__(256) __nv_bfloat16 g_xlo [(size_t)MTOK * EE];
__device__ __align__(256) __nv_bfloat16 g_wahi[(size_t)QKVN * EE];
__device__ __align__(256) __nv_bfloat16 g_walo[(size_t)QKVN * EE];
__device__ __align__(256) __nv_bfloat16 g_wphi[(size_t)EE * EE];
__device__ __align__(256) __nv_bfloat16 g_wplo[(size_t)EE * EE];
__device__ __align__(256) __nv_bfloat16 g_ahi [(size_t)MTOK * EE];
__device__ __align__(256) __nv_bfloat16 g_alo [(size_t)MTOK * EE];

// ---------------- PTX helpers ----------------------------------------------
__device__ __forceinline__ uint32_t smem_u32(const void* p) {
    uint32_t a;
    asm("{ .reg .u64 t; cvta.to.shared.u64 t, %1; cvt.u32.u64 %0, t; }"
        : "=r"(a) : "l"(p));
    return a;
}
#define CP_ASYNC16(sa, g) \
    asm volatile("cp.async.cg.shared.global [%0], [%1], 16;" :: "r"(sa), "l"(g) : "memory")
#define CP_COMMIT() asm volatile("cp.async.commit_group;" ::: "memory")
#define CP_WAIT(n)  asm volatile("cp.async.wait_group %0;" :: "n"(n) : "memory")

__device__ __forceinline__ void ldsm4(uint32_t& r0, uint32_t& r1,
                                      uint32_t& r2, uint32_t& r3, uint32_t a) {
    asm volatile("ldmatrix.sync.aligned.m8n8.x4.shared.b16 {%0,%1,%2,%3}, [%4];"
                 : "=r"(r0), "=r"(r1), "=r"(r2), "=r"(r3) : "r"(a));
}
__device__ __forceinline__ void ldsm4t(uint32_t& r0, uint32_t& r1,
                                       uint32_t& r2, uint32_t& r3, uint32_t a) {
    asm volatile("ldmatrix.sync.aligned.m8n8.x4.trans.shared.b16 {%0,%1,%2,%3}, [%4];"
                 : "=r"(r0), "=r"(r1), "=r"(r2), "=r"(r3) : "r"(a));
}
__device__ __forceinline__ void mma16816(float* c, const uint32_t* a,
                                         const uint32_t* b) {
    asm volatile("mma.sync.aligned.m16n8k16.row.col.f32.bf16.bf16.f32 "
                 "{%0,%1,%2,%3}, {%4,%5,%6,%7}, {%8,%9}, {%0,%1,%2,%3};"
                 : "+f"(c[0]), "+f"(c[1]), "+f"(c[2]), "+f"(c[3])
                 : "r"(a[0]), "r"(a[1]), "r"(a[2]), "r"(a[3]),
                   "r"(b[0]), "r"(b[1]));
}
// pack: lo half = a, hi half = b (memory order [a, b]), round-to-nearest
__device__ __forceinline__ uint32_t packbf(float a, float b) {
    uint32_t r;
    asm("cvt.rn.bf16x2.f32 %0, %1, %2;" : "=r"(r) : "f"(b), "f"(a));
    return r;
}
__device__ __forceinline__ float bfround(float v) {
    return __bfloat162float(__float2bfloat16(v));
}
// SW128 swizzle over 128B rows
__device__ __forceinline__ uint32_t sw_addr(uint32_t base, int row, int chunk) {
    uint32_t off = (uint32_t)(row * 128 + chunk * 16);
    return base + (off ^ ((off >> 3) & 0x70));
}

// ---------------- hi/lo converts --------------------------------------------
__global__ void __launch_bounds__(256) convert_hilo_kernel(
    const float* __restrict__ s, __nv_bfloat16* __restrict__ hi,
    __nv_bfloat16* __restrict__ lo, int n)
{
    int i = blockIdx.x * 256 + threadIdx.x;
    if (i < n) {
        float v = s[i];
        __nv_bfloat16 h = __float2bfloat16(v);
        hi[i] = h;
        lo[i] = __float2bfloat16(v - __bfloat162float(h));
    }
}

__global__ void __launch_bounds__(256) transpose_hilo_kernel(
    const float* __restrict__ W, __nv_bfloat16* __restrict__ Thi,
    __nv_bfloat16* __restrict__ Tlo, int K, int N)   // W[K][N] -> T[N][K]
{
    __shared__ float t[32][33];
    int n0 = blockIdx.x * 32, k0 = blockIdx.y * 32;
    int tx = threadIdx.x, ty = threadIdx.y;
    #pragma unroll
    for (int i = 0; i < 32; i += 8)
        t[ty + i][tx] = W[(size_t)(k0 + ty + i) * N + n0 + tx];
    __syncthreads();
    #pragma unroll
    for (int i = 0; i < 32; i += 8) {
        float v = t[tx][ty + i];
        __nv_bfloat16 h = __float2bfloat16(v);
        size_t o = (size_t)(n0 + ty + i) * K + k0 + tx;
        Thi[o] = h;
        Tlo[o] = __float2bfloat16(v - __bfloat162float(h));
    }
}

// ---------------- HMMA 3-term bf16 GEMM ------------------------------------
#define G3_STAGE   65536
#define G3_STAGES  3
#define G3_SMEM    (G3_STAGES * G3_STAGE)

__device__ __forceinline__ void g3_load_chunk(
    uint32_t sbase, const __nv_bfloat16* Ahi, const __nv_bfloat16* Alo,
    const __nv_bfloat16* Bhi, const __nv_bfloat16* Blo,
    int row0, int col0, int K, int c, int tid)
{
    const __nv_bfloat16* srcs[4];
    srcs[0] = Ahi + (size_t)row0 * K + c * 64;
    srcs[1] = Alo + (size_t)row0 * K + c * 64;
    srcs[2] = Bhi + (size_t)col0 * K + c * 64;
    srcs[3] = Blo + (size_t)col0 * K + c * 64;
    #pragma unroll
    for (int t = 0; t < 4; t++) {
        const __nv_bfloat16* src = srcs[t];
        uint32_t tb = sbase + t * 16384;
        #pragma unroll
        for (int i = 0; i < 4; i++) {
            int idx = tid + i * 256;
            int r = idx >> 3, cb = idx & 7;
            CP_ASYNC16(sw_addr(tb, r, cb), (const void*)(src + (size_t)r * K + cb * 8));
        }
    }
    CP_COMMIT();
}

__global__ void __launch_bounds__(256) gemm3_kernel(
    const __nv_bfloat16* __restrict__ Ahi, const __nv_bfloat16* __restrict__ Alo,
    const __nv_bfloat16* __restrict__ Bhi, const __nv_bfloat16* __restrict__ Blo,
    const float* __restrict__ bias, float* __restrict__ Cf,
    __nv_bfloat16* __restrict__ Chi, __nv_bfloat16* __restrict__ Clo,
    int M, int N, int K)
{
    extern __shared__ __align__(1024) char smg[];
    uint32_t sb = smem_u32(smg);
    const int tid = threadIdx.x;
    const int wid = tid >> 5, lid = tid & 31;
    const int wm = (wid >> 2) * 64;
    const int wn = (wid & 3) * 32;
    const int lrow = lid & 15;
    const int lck  = lid >> 4;
    const int row0 = blockIdx.y * 128, col0 = blockIdx.x * 128;
    const int nch = K / 64;

    float acc[4][4][4];
    #pragma unroll
    for (int mi = 0; mi < 4; mi++)
        #pragma unroll
        for (int nj = 0; nj < 4; nj++)
            #pragma unroll
            for (int r = 0; r < 4; r++) acc[mi][nj][r] = 0.0f;

    g3_load_chunk(sb,               Ahi, Alo, Bhi, Blo, row0, col0, K, 0, tid);
    g3_load_chunk(sb + G3_STAGE,    Ahi, Alo, Bhi, Blo, row0, col0, K, 1, tid);
    g3_load_chunk(sb + 2*G3_STAGE,  Ahi, Alo, Bhi, Blo, row0, col0, K, 2, tid);

    for (int c = 0; c < nch; c++) {
        CP_WAIT(2);
        __syncthreads();
        uint32_t st = sb + (uint32_t)(c % G3_STAGES) * G3_STAGE;
        uint32_t bAh = st, bAl = st + 16384, bBh = st + 32768, bBl = st + 49152;

        #pragma unroll
        for (int step = 0; step < 4; step++) {
            int kc = 2 * step;
            uint32_t ah[4][4], al[4][4], bh[4][2], bl[4][2];
            #pragma unroll
            for (int mi = 0; mi < 4; mi++) {
                ldsm4(ah[mi][0], ah[mi][1], ah[mi][2], ah[mi][3],
                      sw_addr(bAh, wm + mi * 16 + lrow, kc + lck));
                ldsm4(al[mi][0], al[mi][1], al[mi][2], al[mi][3],
                      sw_addr(bAl, wm + mi * 16 + lrow, kc + lck));
            }
            #pragma unroll
            for (int g = 0; g < 2; g++) {
                uint32_t r0, r1, r2, r3;
                ldsm4(r0, r1, r2, r3, sw_addr(bBh, wn + g * 16 + lrow, kc + lck));
                bh[2*g][0] = r0; bh[2*g+1][0] = r1; bh[2*g][1] = r2; bh[2*g+1][1] = r3;
                ldsm4(r0, r1, r2, r3, sw_addr(bBl, wn + g * 16 + lrow, kc + lck));
                bl[2*g][0] = r0; bl[2*g+1][0] = r1; bl[2*g][1] = r2; bl[2*g+1][1] = r3;
            }
            #pragma unroll
            for (int mi = 0; mi < 4; mi++)
                #pragma unroll
                for (int nj = 0; nj < 4; nj++) {
                    mma16816(acc[mi][nj], ah[mi], bh[nj]);
                    mma16816(acc[mi][nj], ah[mi], bl[nj]);
                    mma16816(acc[mi][nj], al[mi], bh[nj]);
                }
        }
        __syncthreads();
        if (c + G3_STAGES < nch)
            g3_load_chunk(st, Ahi, Alo, Bhi, Blo, row0, col0, K, c + G3_STAGES, tid);
    }

    const int gID = lid >> 2, tig = lid & 3;
    #pragma unroll
    for (int mi = 0; mi < 4; mi++) {
        int r = row0 + wm + mi * 16 + gID;
        #pragma unroll
        for (int nj = 0; nj < 4; nj++) {
            int cc = col0 + wn + nj * 8 + tig * 2;
            float b0 = bias[cc], b1 = bias[cc + 1];
            float v0 = acc[mi][nj][0] + b0, v1 = acc[mi][nj][1] + b1;
            float v2 = acc[mi][nj][2] + b0, v3 = acc[mi][nj][3] + b1;
            if (Cf) {
                *(float2*)&Cf[(size_t)r * N + cc] = make_float2(v0, v1);
                *(float2*)&Cf[(size_t)(r + 8) * N + cc] = make_float2(v2, v3);
            } else {
                *(uint32_t*)&Chi[(size_t)r * N + cc] = packbf(v0, v1);
                *(uint32_t*)&Clo[(size_t)r * N + cc] =
                    packbf(v0 - bfround(v0), v1 - bfround(v1));
                *(uint32_t*)&Chi[(size_t)(r + 8) * N + cc] = packbf(v2, v3);
                *(uint32_t*)&Clo[(size_t)(r + 8) * N + cc] =
                    packbf(v2 - bfround(v2), v3 - bfround(v3));
            }
        }
    }
}

// ---------------- HMMA causal flash attention -------------------------------
// CTA: 128 q-rows x 1 head. 8 warps x 16 rows. Bc=64 keys, double-buffered.
// smem: Qhi(16K) Qlo(16K) + 2 stages x [Khi Klo Vhi Vlo](8K each) = 96KB.
#define ATT_SMEM 98304

__device__ __forceinline__ void att_load_kv(
    uint32_t stbase, const __nv_bfloat16* qkvhi, const __nv_bfloat16* qkvlo,
    size_t tokbase, int kcol, int vcol, int kt, int tid)
{
    const __nv_bfloat16* srcs[4];
    srcs[0] = qkvhi + (tokbase + kt * 64) * QKVN + kcol;
    srcs[1] = qkvlo + (tokbase + kt * 64) * QKVN + kcol;
    srcs[2] = qkvhi + (tokbase + kt * 64) * QKVN + vcol;
    srcs[3] = qkvlo + (tokbase + kt * 64) * QKVN + vcol;
    #pragma unroll
    for (int t = 0; t < 4; t++) {
        uint32_t tb = stbase + t * 8192;
        #pragma unroll
        for (int i = 0; i < 2; i++) {
            int idx = tid + i * 256;
            int r = idx >> 3, cb = idx & 7;
            CP_ASYNC16(sw_addr(tb, r, cb), (const void*)(srcs[t] + (size_t)r * QKVN + cb * 8));
        }
    }
    CP_COMMIT();
}

__global__ void __launch_bounds__(256) attn_hmma_kernel(
    const __nv_bfloat16* __restrict__ qkvhi, const __nv_bfloat16* __restrict__ qkvlo,
    __nv_bfloat16* __restrict__ ohi, __nv_bfloat16* __restrict__ olo)
{
    extern __shared__ __align__(1024) char sma[];
    uint32_t sb = smem_u32(sma);
    const int tid = threadIdx.x, wid = tid >> 5, lid = tid & 31;
    const int lrow = lid & 15, lck = lid >> 4, gID = lid >> 2, tig = lid & 3;
    const int wm = wid * 16;
    const int bh = blockIdx.x;
    const int b = bh / NH, h = bh % NH;
    const int qt = gridDim.y - 1 - blockIdx.y;     // long tiles first
    const int q0 = qt * 128;
    const size_t tokbase = (size_t)b * SS;
    const int qcol = h * 64, kcol = EE + h * 64, vcol = 2 * EE + h * 64;
    const int ntiles = 2 * qt + 2;

    const uint32_t sQh = sb, sQl = sb + 16384;

    // Q hi/lo (128 rows x 64)
    {
        const __nv_bfloat16* qh = qkvhi + (tokbase + q0) * QKVN + qcol;
        const __nv_bfloat16* ql = qkvlo + (tokbase + q0) * QKVN + qcol;
        #pragma unroll
        for (int i = 0; i < 4; i++) {
            int idx = tid + i * 256;
            int r = idx >> 3, cb = idx & 7;
            CP_ASYNC16(sw_addr(sQh, r, cb), (const void*)(qh + (size_t)r * QKVN + cb * 8));
            CP_ASYNC16(sw_addr(sQl, r, cb), (const void*)(ql + (size_t)r * QKVN + cb * 8));
        }
    }
    att_load_kv(sb + 32768, qkvhi, qkvlo, tokbase, kcol, vcol, 0, tid);           // group: Q+KV0
    att_load_kv(sb + 32768 + 32768, qkvhi, qkvlo, tokbase, kcol, vcol, 1, tid);   // group: KV1

    float m0 = -1e30f, m1 = -1e30f, l0 = 0.0f, l1 = 0.0f;
    float of[8][4];
    #pragma unroll
    for (int j = 0; j < 8; j++)
        #pragma unroll
        for (int e = 0; e < 4; e++) of[j][e] = 0.0f;

    uint32_t qh[4][4], ql[4][4];
    bool qloaded = false;

    for (int kt = 0; kt < ntiles; kt++) {
        if (kt + 1 < ntiles) { CP_WAIT(1); } else { CP_WAIT(0); }
        __syncthreads();
        if (!qloaded) {
            #pragma unroll
            for (int ks = 0; ks < 4; ks++) {
                ldsm4(qh[ks][0], qh[ks][1], qh[ks][2], qh[ks][3],
                      sw_addr(sQh, wm + lrow, 2 * ks + lck));
                ldsm4(ql[ks][0], ql[ks][1], ql[ks][2], ql[ks][3],
                      sw_addr(sQl, wm + lrow, 2 * ks + lck));
            }
            qloaded = true;
        }
        const uint32_t st = sb + 32768 + (uint32_t)(kt & 1) * 32768;
        const bool active = (kt * 64 <= q0 + wm + 15);

        if (active) {
            // ---- S = (Qhi+Qlo)(Khi+Klo)^T, 3 terms ----
            float sf[8][4];
            #pragma unroll
            for (int j = 0; j < 8; j++)
                #pragma unroll
                for (int e = 0; e < 4; e++) sf[j][e] = 0.0f;
            #pragma unroll
            for (int ks = 0; ks < 4; ks++) {
                #pragma unroll
                for (int g = 0; g < 4; g++) {
                    uint32_t kh[2][2], kl[2][2], r0, r1, r2, r3;
                    ldsm4(r0, r1, r2, r3, sw_addr(st, g * 16 + lrow, 2 * ks + lck));
                    kh[0][0] = r0; kh[1][0] = r1; kh[0][1] = r2; kh[1][1] = r3;
                    ldsm4(r0, r1, r2, r3, sw_addr(st + 8192, g * 16 + lrow, 2 * ks + lck));
                    kl[0][0] = r0; kl[1][0] = r1; kl[0][1] = r2; kl[1][1] = r3;
                    #pragma unroll
                    for (int u = 0; u < 2; u++) {
                        mma16816(sf[2 * g + u], qh[ks], kh[u]);
                        mma16816(sf[2 * g + u], qh[ks], kl[u]);
                        mma16816(sf[2 * g + u], ql[ks], kh[u]);
                    }
                }
            }

            // ---- scale + causal mask ----
            const bool masked = (kt * 64 + 63 > q0 + wm);
            #pragma unroll
            for (int j = 0; j < 8; j++) {
                #pragma unroll
                for (int e = 0; e < 4; e++) {
                    float v = sf[j][e] * 0.125f;
                    if (masked) {
                        int c = kt * 64 + 8 * j + tig * 2 + (e & 1);
                        int r = q0 + wm + gID + (e >> 1) * 8;
                        if (c > r) v = -1e30f;
                    }
                    sf[j][e] = v;
                }
            }

            // ---- online softmax ----
            float mt0 = -1e30f, mt1 = -1e30f;
            #pragma unroll
            for (int j = 0; j < 8; j++) {
                mt0 = fmaxf(mt0, fmaxf(sf[j][0], sf[j][1]));
                mt1 = fmaxf(mt1, fmaxf(sf[j][2], sf[j][3]));
            }
            mt0 = fmaxf(mt0, __shfl_xor_sync(0xffffffffu, mt0, 1));
            mt0 = fmaxf(mt0, __shfl_xor_sync(0xffffffffu, mt0, 2));
            mt1 = fmaxf(mt1, __shfl_xor_sync(0xffffffffu, mt1, 1));
            mt1 = fmaxf(mt1, __shfl_xor_sync(0xffffffffu, mt1, 2));
            float mn0 = fmaxf(m0, mt0), mn1 = fmaxf(m1, mt1);
            float a0 = __expf(m0 - mn0), a1 = __expf(m1 - mn1);
            m0 = mn0; m1 = mn1;

            float sum0 = 0.0f, sum1 = 0.0f;
            uint32_t ph[4][4], pl[4][4];
            #pragma unroll
            for (int j = 0; j < 8; j++) {
                float p0 = __expf(sf[j][0] - mn0), p1 = __expf(sf[j][1] - mn0);
                float p2 = __expf(sf[j][2] - mn1), p3 = __expf(sf[j][3] - mn1);
                sum0 += p0 + p1; sum1 += p2 + p3;
                int ks = j >> 1, half = (j & 1) * 2;
                ph[ks][half + 0] = packbf(p0, p1);
                ph[ks][half + 1] = packbf(p2, p3);
                pl[ks][half + 0] = packbf(p0 - bfround(p0), p1 - bfround(p1));
                pl[ks][half + 1] = packbf(p2 - bfround(p2), p3 - bfround(p3));
            }
            sum0 += __shfl_xor_sync(0xffffffffu, sum0, 1);
            sum0 += __shfl_xor_sync(0xffffffffu, sum0, 2);
            sum1 += __shfl_xor_sync(0xffffffffu, sum1, 1);
            sum1 += __shfl_xor_sync(0xffffffffu, sum1, 2);
            l0 = l0 * a0 + sum0; l1 = l1 * a1 + sum1;
            #pragma unroll
            for (int j = 0; j < 8; j++) {
                of[j][0] *= a0; of[j][1] *= a0; of[j][2] *= a1; of[j][3] *= a1;
            }

            // ---- O += (Phi+Plo)(Vhi+Vlo), 3 terms; V via ldmatrix.trans ----
            const uint32_t sVh = st + 16384, sVl = st + 24576;
            #pragma unroll
            for (int ks = 0; ks < 4; ks++) {
                #pragma unroll
                for (int dg = 0; dg < 4; dg++) {
                    uint32_t vh[2][2], vl[2][2], r0, r1, r2, r3;
                    ldsm4t(r0, r1, r2, r3, sw_addr(sVh, ks * 16 + lrow, 2 * dg + lck));
                    vh[0][0] = r0; vh[0][1] = r1; vh[1][0] = r2; vh[1][1] = r3;
                    ldsm4t(r0, r1, r2, r3, sw_addr(sVl, ks * 16 + lrow, 2 * dg + lck));
                    vl[0][0] = r0; vl[0][1] = r1; vl[1][0] = r2; vl[1][1] = r3;
                    #pragma unroll
                    for (int u = 0; u < 2; u++) {
                        mma16816(of[2 * dg + u], ph[ks], vh[u]);
                        mma16816(of[2 * dg + u], ph[ks], vl[u]);
                        mma16816(of[2 * dg + u], pl[ks], vh[u]);
                    }
                }
            }
        }

        __syncthreads();
        if (kt + 2 < ntiles)
            att_load_kv(sb + 32768 + (uint32_t)(kt & 1) * 32768,
                        qkvhi, qkvlo, tokbase, kcol, vcol, kt + 2, tid);
    }

    // ---- normalize + write hi/lo ----
    float inv0 = 1.0f / l0, inv1 = 1.0f / l1;
    size_t row0 = (tokbase + q0 + wm + gID) * EE;
    size_t row1 = (tokbase + q0 + wm + gID + 8) * EE;
    #pragma unroll
    for (int j = 0; j < 8; j++) {
        int d = h * 64 + 8 * j + tig * 2;
        float v0 = of[j][0] * inv0, v1 = of[j][1] * inv0;
        float v2 = of[j][2] * inv1, v3 = of[j][3] * inv1;
        *(uint32_t*)&ohi[row0 + d] = packbf(v0, v1);
        *(uint32_t*)&olo[row0 + d] = packbf(v0 - bfround(v0), v1 - bfround(v1));
        *(uint32_t*)&ohi[row1 + d] = packbf(v2, v3);
        *(uint32_t*)&olo[row1 + d] = packbf(v2 - bfround(v2), v3 - bfround(v3));
    }
}

// ---------------------------------------------------------------------------
extern "C" void kernel_launch(void* const* d_in, const int* in_sizes, int n_in,
                              void* d_out, int out_size)
{
    (void)in_sizes; (void)n_in; (void)out_size;
    const float* x      = (const float*)d_in[0];
    // d_in[1] = mask — strict-upper-triangular causal mask, applied analytically
    const float* W_attn = (const float*)d_in[2];
    const float* b_attn = (const float*)d_in[3];
    const float* W_proj = (const float*)d_in[4];
    const float* b_proj = (const float*)d_in[5];
    float* out = (float*)d_out;

    __nv_bfloat16 *qhi, *qlo, *xhi, *xlo, *wahi, *walo, *wphi, *wplo, *ahi, *alo;
    cudaGetSymbolAddress((void**)&qhi,  g_qkvhi);
    cudaGetSymbolAddress((void**)&qlo,  g_qkvlo);
    cudaGetSymbolAddress((void**)&xhi,  g_xhi);
    cudaGetSymbolAddress((void**)&xlo,  g_xlo);
    cudaGetSymbolAddress((void**)&wahi, g_wahi);
    cudaGetSymbolAddress((void**)&walo, g_walo);
    cudaGetSymbolAddress((void**)&wphi, g_wphi);
    cudaGetSymbolAddress((void**)&wplo, g_wplo);
    cudaGetSymbolAddress((void**)&ahi,  g_ahi);
    cudaGetSymbolAddress((void**)&alo,  g_alo);

    cudaFuncSetAttribute(gemm3_kernel,
                         cudaFuncAttributeMaxDynamicSharedMemorySize, G3_SMEM);
    cudaFuncSetAttribute(attn_hmma_kernel,
                         cudaFuncAttributeMaxDynamicSharedMemorySize, ATT_SMEM);

    // 0) operand prep
    {
        int n = MTOK * EE;
        convert_hilo_kernel<<<(n + 255) / 256, 256>>>(x, xhi, xlo, n);
        transpose_hilo_kernel<<<dim3(QKVN / 32, EE / 32), dim3(32, 8)>>>(
            W_attn, wahi, walo, EE, QKVN);
        transpose_hilo_kernel<<<dim3(EE / 32, EE / 32), dim3(32, 8)>>>(
            W_proj, wphi, wplo, EE, EE);
    }
    // 1) QKV projection -> bf16 hi/lo qkv
    gemm3_kernel<<<dim3(QKVN / 128, MTOK / 128), 256, G3_SMEM>>>(
        xhi, xlo, wahi, walo, b_attn, nullptr, qhi, qlo, MTOK, QKVN, EE);
    // 2) causal flash attention (HMMA, 3-term) -> bf16 hi/lo
    attn_hmma_kernel<<<dim3(BB * NH, SS / 128), 256, ATT_SMEM>>>(qhi, qlo, ahi, alo);
    // 3) output projection -> f32 out
    gemm3_kernel<<<dim3(EE / 128, MTOK / 128), 256, G3_SMEM>>>(
        ahi, alo, wphi, wplo, b_proj, out, nullptr, nullptr, MTOK, EE, EE);
}